// round 14
// baseline (speedup 1.0000x reference)
#include <cuda_runtime.h>
#include <cuda_bf16.h>
#include <math.h>
#include <stdint.h>

#define BB 256
#define SS 128
#define EE 512
#define HH 1024
#define VV 128
#define CC 18

// ---------------- device scratch (no cudaMalloc allowed) ----------------
__device__ float          g_T[VV * HH];     // T[v][h] = W_ih.emb[v] + b_ih + b_hh
__device__ __nv_bfloat16  g_ah[BB * HH];    // h split hi (bf16)
__device__ __nv_bfloat16  g_al[BB * HH];    // h split lo (bf16)
__device__ __nv_bfloat16  g_wh[HH * HH];    // W_hh split hi
__device__ __nv_bfloat16  g_wl[HH * HH];    // W_hh split lo
__device__ float          g_last[BB * HH];
__device__ float          g_mlp1[BB * HH];
__device__ int            g_xin[BB * SS];
__device__ int            g_len[BB];
__device__ int            g_cnt[4];
__device__ volatile int   g_sense[4];

// ---------------------------------------------------------------------------
// Preprocessing
// ---------------------------------------------------------------------------
__global__ void __launch_bounds__(256) convert_inputs(const void* xin_raw,
                                                      const void* xlen_raw) {
    long long probe = ((const long long*)xlen_raw)[0];
    bool is64 = (probe >= 1 && probe <= SS);
    int i = blockIdx.x * blockDim.x + threadIdx.x;
    if (i < BB * SS) {
        g_xin[i] = is64 ? (int)((const long long*)xin_raw)[i]
                        : ((const int*)xin_raw)[i];
    }
    if (i < BB) {
        g_len[i] = is64 ? (int)((const long long*)xlen_raw)[i]
                        : ((const int*)xlen_raw)[i];
    }
}

__global__ void __launch_bounds__(256) split_whh(const float* __restrict__ W) {
    int i = blockIdx.x * blockDim.x + threadIdx.x;
    if (i < HH * HH) {
        float w = W[i];
        __nv_bfloat16 hi = __float2bfloat16_rn(w);
        float lo = w - __bfloat162float(hi);
        g_wh[i] = hi;
        g_wl[i] = __float2bfloat16_rn(lo);
    }
}

// ---------------------------------------------------------------------------
// Generic tiled GEMM (aux)
// ---------------------------------------------------------------------------
__global__ void __launch_bounds__(256) gemm_bias_act(
    const float* __restrict__ A, const float* __restrict__ Bm,
    const float* __restrict__ bias, const float* __restrict__ bias2,
    float* __restrict__ Cout, int M, int N, int K, int act)
{
    __shared__ float As[32][33];
    __shared__ float Bs[32][65];

    const int tid = threadIdx.x;
    const int tx = tid & 15;
    const int ty = tid >> 4;
    const int m0 = blockIdx.y * 32;
    const int n0 = blockIdx.x * 64;
    const int ka = tid & 31;
    const int ra = tid >> 5;

    float acc[2][4] = {};

    for (int k0 = 0; k0 < K; k0 += 32) {
        #pragma unroll
        for (int r = 0; r < 4; r++)
            As[ka][ra + r * 8] = A[(size_t)(m0 + ra + r * 8) * K + k0 + ka];
        #pragma unroll
        for (int r = 0; r < 8; r++) {
            int n = ra + r * 8;
            float v = 0.0f;
            if (n0 + n < N) v = Bm[(size_t)(n0 + n) * K + k0 + ka];
            Bs[ka][n] = v;
        }
        __syncthreads();
        #pragma unroll
        for (int kk = 0; kk < 32; kk++) {
            float a[2], b[4];
            #pragma unroll
            for (int i = 0; i < 2; i++) a[i] = As[kk][ty * 2 + i];
            #pragma unroll
            for (int j = 0; j < 4; j++) b[j] = Bs[kk][tx * 4 + j];
            #pragma unroll
            for (int i = 0; i < 2; i++)
                #pragma unroll
                for (int j = 0; j < 4; j++)
                    acc[i][j] = fmaf(a[i], b[j], acc[i][j]);
        }
        __syncthreads();
    }

    #pragma unroll
    for (int i = 0; i < 2; i++) {
        int m = m0 + ty * 2 + i;
        if (m >= M) continue;
        #pragma unroll
        for (int j = 0; j < 4; j++) {
            int n = n0 + tx * 4 + j;
            if (n >= N) continue;
            float z = acc[i][j] + bias[n];
            if (bias2) z += bias2[n];
            if (act == 1) z = fmaxf(z, 0.0f);
            Cout[(size_t)m * N + n] = z;
        }
    }
}

// ---------------------------------------------------------------------------
// Persistent RNN on tensor cores, k-split warps.
// 128 CTAs = 4 m-groups (64 rows) x 32 n-blocks (32 cols), 512 threads.
// Warps: 2m x 1n x 8k. Warp tile m32 x n32, k-warp kw owns kpairs
// [8kw, 8kw+8) of each streamed k128 chunk. W (hi+lo) resident in smem.
// Per step: 8 chunks (ping-pong, register prefetch), 24 MMA/warp/chunk,
// then 8-way k-reduction through smem; epilogue spread over all 512 threads.
// ---------------------------------------------------------------------------
#define WS 516                       // u32 stride per W row (512 + 4 pad)
#define AS 68                        // u32 stride per A row (64 + 4 pad)
#define WH_OFF 0
#define WL_OFF (32 * WS)             // 16512
#define AB_OFF (2 * 32 * WS)         // 33024
#define A_CH   (64 * AS)             // 4352 u32 per chunk (one split)
#define AB_STEP (2 * A_CH)           // hi+lo per buffer = 8704
#define SMEM_U32 (AB_OFF + 2 * AB_STEP)
#define SMEM_BYTES (SMEM_U32 * 4)    // 201728

// reduction region reuses both A buffers: 8 partial blocks, stride 2176 u32
#define RB_OFF AB_OFF
#define RB_STRIDE 2176               // 64 rows * 34
#define RROW 34                      // f32 stride per output row (32 + 2 pad)

#define MMA(c, A0, A1, A2, A3, B0, B1) \
    asm volatile( \
        "mma.sync.aligned.m16n8k16.row.col.f32.bf16.bf16.f32 " \
        "{%0,%1,%2,%3}, {%4,%5,%6,%7}, {%8,%9}, {%0,%1,%2,%3};" \
        : "+f"((c)[0]), "+f"((c)[1]), "+f"((c)[2]), "+f"((c)[3]) \
        : "r"(A0), "r"(A1), "r"(A2), "r"(A3), "r"(B0), "r"(B1))

__global__ void __launch_bounds__(512, 1) rnn_mma()
{
    extern __shared__ uint32_t sm[];
    float* smf = (float*)sm;

    const int tid = threadIdx.x;
    const int wid = tid >> 5;
    const int lid = tid & 31;
    const int gi = blockIdx.x >> 5;        // m-group 0..3
    const int gj = blockIdx.x & 31;        // n-block 0..31
    const int m0 = gi * 64;
    const int n0 = gj * 32;

    const int g = lid >> 2;                // 0..7
    const int q = lid & 3;                 // 0..3
    const int wm = wid & 1;                // m-warp 0..1
    const int kw = wid >> 1;               // k-warp 0..7
    const int mwl = 32 * wm;               // local row base (m32 tile)

    // ---- load resident W (hi+lo) k-major into smem ----
    {
        const uint4* gwh = (const uint4*)g_wh;
        const uint4* gwl = (const uint4*)g_wl;
        for (int idx = tid; idx < 32 * 128; idx += 512) {
            int row = idx >> 7;            // 0..31
            int slot = idx & 127;          // uint4 slot (4 kpairs)
            uint4 vh = gwh[(size_t)(n0 + row) * 128 + slot];
            uint4 vl = gwl[(size_t)(n0 + row) * 128 + slot];
            *(uint4*)(sm + WH_OFF + row * WS + slot * 4) = vh;
            *(uint4*)(sm + WL_OFF + row * WS + slot * 4) = vl;
        }
    }
    __syncthreads();

    // per-lane fragment bases
    // A rows: (mwl + tm*16 + g) and +8 ; kpair: kw*8 + q (+4)
    const int ar0 = (mwl + g) * AS + q;          // tm=0
    const int ar1 = (mwl + 16 + g) * AS + q;     // tm=1
    const int ka = kw * 8;
    // B cols: tn*8 + g ; kpair: c*64 + kw*8 + q (+4)
    const int wbh = (g) * WS + q;                // tn adds 8*WS
    const int wbl = wbh + WL_OFF;

    // staging coords: rows st_r, st_r+32 ; uint4 slot st_s
    const int st_r = tid >> 4;             // 0..31
    const int st_s = tid & 15;             // 0..15

    // epilogue coords: one row, 4 cols per thread
    const int ep_r = tid >> 3;             // 0..63
    const int ep_c = (tid & 7) * 4;        // 0,4,..28
    const int ep_m = m0 + ep_r;
    const int ep_len = g_len[ep_m];

    const uint4* gah = (const uint4*)g_ah;
    const uint4* gal = (const uint4*)g_al;

    for (int t = 0; t < SS; t++) {
        float acc[2][4][4];
        #pragma unroll
        for (int i = 0; i < 2; i++)
            #pragma unroll
            for (int j = 0; j < 4; j++)
                #pragma unroll
                for (int r = 0; r < 4; r++) acc[i][j][r] = 0.f;

        if (t > 0) {
            uint4 pfh[2], pfl[2];
            // prefetch + store chunk 0
            #pragma unroll
            for (int j = 0; j < 2; j++) {
                int row = st_r + 32 * j;
                size_t gidx = (size_t)(m0 + row) * 128 + st_s;
                pfh[j] = __ldcg(gah + gidx);
                pfl[j] = __ldcg(gal + gidx);
            }
            #pragma unroll
            for (int j = 0; j < 2; j++) {
                int row = st_r + 32 * j;
                *(uint4*)(sm + AB_OFF + row * AS + st_s * 4) = pfh[j];
                *(uint4*)(sm + AB_OFF + A_CH + row * AS + st_s * 4) = pfl[j];
            }
            __syncthreads();

            for (int c = 0; c < 8; c++) {
                // prefetch chunk c+1
                if (c + 1 < 8) {
                    #pragma unroll
                    for (int j = 0; j < 2; j++) {
                        int row = st_r + 32 * j;
                        size_t gidx = (size_t)(m0 + row) * 128 + (c + 1) * 16 + st_s;
                        pfh[j] = __ldcg(gah + gidx);
                        pfl[j] = __ldcg(gal + gidx);
                    }
                }

                // compute: this k-warp's 8 kpairs (one k16 step) of chunk c
                const int ab = AB_OFF + (c & 1) * AB_STEP;
                const int kwp = c * 64 + kw * 8;

                uint32_t ah0 = sm[ab + ar0 + ka];
                uint32_t ah1 = sm[ab + ar0 + 8 * AS + ka];
                uint32_t ah2 = sm[ab + ar0 + ka + 4];
                uint32_t ah3 = sm[ab + ar0 + 8 * AS + ka + 4];
                uint32_t bh0t0 = sm[wbh + kwp];
                uint32_t bh1t0 = sm[wbh + kwp + 4];

                uint32_t ag0 = sm[ab + ar1 + ka];
                uint32_t ag1 = sm[ab + ar1 + 8 * AS + ka];
                uint32_t ag2 = sm[ab + ar1 + ka + 4];
                uint32_t ag3 = sm[ab + ar1 + 8 * AS + ka + 4];

                uint32_t am0 = sm[ab + A_CH + ar0 + ka];
                uint32_t am1 = sm[ab + A_CH + ar0 + 8 * AS + ka];
                uint32_t am2 = sm[ab + A_CH + ar0 + ka + 4];
                uint32_t am3 = sm[ab + A_CH + ar0 + 8 * AS + ka + 4];
                uint32_t an0 = sm[ab + A_CH + ar1 + ka];
                uint32_t an1 = sm[ab + A_CH + ar1 + 8 * AS + ka];
                uint32_t an2 = sm[ab + A_CH + ar1 + ka + 4];
                uint32_t an3 = sm[ab + A_CH + ar1 + 8 * AS + ka + 4];

                #pragma unroll
                for (int tn = 0; tn < 4; tn++) {
                    uint32_t bh0 = (tn == 0) ? bh0t0 : sm[wbh + tn * 8 * WS + kwp];
                    uint32_t bh1 = (tn == 0) ? bh1t0 : sm[wbh + tn * 8 * WS + kwp + 4];
                    uint32_t bl0 = sm[wbl + tn * 8 * WS + kwp];
                    uint32_t bl1 = sm[wbl + tn * 8 * WS + kwp + 4];
                    // hi*hi
                    MMA(acc[0][tn], ah0, ah1, ah2, ah3, bh0, bh1);
                    MMA(acc[1][tn], ag0, ag1, ag2, ag3, bh0, bh1);
                    // hi*lo
                    MMA(acc[0][tn], ah0, ah1, ah2, ah3, bl0, bl1);
                    MMA(acc[1][tn], ag0, ag1, ag2, ag3, bl0, bl1);
                    // lo*hi
                    MMA(acc[0][tn], am0, am1, am2, am3, bh0, bh1);
                    MMA(acc[1][tn], an0, an1, an2, an3, bh0, bh1);
                }

                // store prefetched chunk
                if (c + 1 < 8) {
                    const int db = AB_OFF + ((c + 1) & 1) * AB_STEP;
                    #pragma unroll
                    for (int j = 0; j < 2; j++) {
                        int row = st_r + 32 * j;
                        *(uint4*)(sm + db + row * AS + st_s * 4) = pfh[j];
                        *(uint4*)(sm + db + A_CH + row * AS + st_s * 4) = pfl[j];
                    }
                }
                __syncthreads();
            }

            // ---- write k-partials to smem (reuse A buffers) ----
            {
                const int base = RB_OFF + kw * RB_STRIDE;
                #pragma unroll
                for (int tm = 0; tm < 2; tm++) {
                    int row = mwl + tm * 16 + g;
                    #pragma unroll
                    for (int tn = 0; tn < 4; tn++) {
                        int col = tn * 8 + 2 * q;
                        *(float2*)(smf + base + row * RROW + col) =
                            make_float2(acc[tm][tn][0], acc[tm][tn][1]);
                        *(float2*)(smf + base + (row + 8) * RROW + col) =
                            make_float2(acc[tm][tn][2], acc[tm][tn][3]);
                    }
                }
            }
            __syncthreads();
        }

        // ---- epilogue: 1 row x 4 cols per thread, all 512 threads ----
        {
            int xi = g_xin[ep_m * SS + t];
            float4 tv = *(const float4*)(g_T + (size_t)xi * HH + n0 + ep_c);
            float v0 = tv.x, v1 = tv.y, v2 = tv.z, v3 = tv.w;
            if (t > 0) {
                #pragma unroll
                for (int p = 0; p < 8; p++) {
                    const float* pb = smf + RB_OFF + p * RB_STRIDE
                                    + ep_r * RROW + ep_c;
                    v0 += pb[0]; v1 += pb[1]; v2 += pb[2]; v3 += pb[3];
                }
            }
            v0 = tanhf(v0); v1 = tanhf(v1); v2 = tanhf(v2); v3 = tanhf(v3);

            __nv_bfloat16 h0 = __float2bfloat16_rn(v0);
            __nv_bfloat16 h1 = __float2bfloat16_rn(v1);
            __nv_bfloat16 h2 = __float2bfloat16_rn(v2);
            __nv_bfloat16 h3 = __float2bfloat16_rn(v3);
            __nv_bfloat16 l0 = __float2bfloat16_rn(v0 - __bfloat162float(h0));
            __nv_bfloat16 l1 = __float2bfloat16_rn(v1 - __bfloat162float(h1));
            __nv_bfloat16 l2 = __float2bfloat16_rn(v2 - __bfloat162float(h2));
            __nv_bfloat16 l3 = __float2bfloat16_rn(v3 - __bfloat162float(h3));

            uint32_t* ph = (uint32_t*)g_ah + (size_t)ep_m * (HH / 2)
                         + (n0 + ep_c) / 2;
            uint32_t* pl = (uint32_t*)g_al + (size_t)ep_m * (HH / 2)
                         + (n0 + ep_c) / 2;
            ph[0] = (uint32_t)__bfloat16_as_ushort(h0)
                  | ((uint32_t)__bfloat16_as_ushort(h1) << 16);
            ph[1] = (uint32_t)__bfloat16_as_ushort(h2)
                  | ((uint32_t)__bfloat16_as_ushort(h3) << 16);
            pl[0] = (uint32_t)__bfloat16_as_ushort(l0)
                  | ((uint32_t)__bfloat16_as_ushort(l1) << 16);
            pl[1] = (uint32_t)__bfloat16_as_ushort(l2)
                  | ((uint32_t)__bfloat16_as_ushort(l3) << 16);

            if (t == ep_len - 1) {
                *(float4*)(g_last + (size_t)ep_m * HH + n0 + ep_c) =
                    make_float4(v0, v1, v2, v3);
            }
        }

        // ---- per-m-group barrier (32 CTAs), replay-safe ----
        __syncthreads();
        if (tid == 0) {
            __threadfence();
            int target = (t + 1) & 127;
            int arrived = atomicAdd(&g_cnt[gi], 1);
            if (arrived == 31) {
                g_cnt[gi] = 0;
                __threadfence();
                g_sense[gi] = target;
            } else {
                while (g_sense[gi] != target) { }
                __threadfence();
            }
        }
        __syncthreads();
    }
}

extern "C" void kernel_launch(void* const* d_in, const int* in_sizes, int n_in,
                              void* d_out, int out_size) {
    const void*  x_in  = d_in[0];
    const void*  xlen  = d_in[1];
    const float* emb   = (const float*)d_in[2];
    const float* W_ih  = (const float*)d_in[3];
    const float* b_ih  = (const float*)d_in[4];
    const float* W_hh  = (const float*)d_in[5];
    const float* b_hh  = (const float*)d_in[6];
    const float* W1    = (const float*)d_in[7];
    const float* b1    = (const float*)d_in[8];
    const float* W2    = (const float*)d_in[9];
    const float* b2    = (const float*)d_in[10];
    float* out = (float*)d_out;

    float *Tp, *lastp, *mlp1p;
    cudaGetSymbolAddress((void**)&Tp,    g_T);
    cudaGetSymbolAddress((void**)&lastp, g_last);
    cudaGetSymbolAddress((void**)&mlp1p, g_mlp1);

    cudaFuncSetAttribute(rnn_mma,
                         cudaFuncAttributeMaxDynamicSharedMemorySize, SMEM_BYTES);

    convert_inputs<<<(BB * SS + 255) / 256, 256>>>(x_in, xlen);
    split_whh<<<(HH * HH + 255) / 256, 256>>>(W_hh);

    // T[v][h] = emb[v]·W_ih[h] + b_ih[h] + b_hh[h]
    gemm_bias_act<<<dim3(HH / 64, VV / 32), 256>>>(emb, W_ih, b_ih, b_hh, Tp,
                                                   VV, HH, EE, 0);

    // Persistent tensor-core RNN over all 128 steps.
    rnn_mma<<<128, 512, SMEM_BYTES>>>();

    // MLP head.
    gemm_bias_act<<<dim3(HH / 64, BB / 32), 256>>>(lastp, W1, b1, nullptr, mlp1p,
                                                   BB, HH, HH, 1);
    gemm_bias_act<<<dim3(1, BB / 32), 256>>>(mlp1p, W2, b2, nullptr, out,
                                             BB, CC, HH, 0);
}

// round 16
// speedup vs baseline: 1.9969x; 1.9969x over previous
#include <cuda_runtime.h>
#include <cuda_bf16.h>
#include <math.h>
#include <stdint.h>

#define BB 256
#define SS 128
#define EE 512
#define HH 1024
#define VV 128
#define CC 18

// ---------------- device scratch (no cudaMalloc allowed) ----------------
__device__ float          g_T[VV * HH];     // T[v][h] = W_ih.emb[v] + b_ih + b_hh
// h as m16n8k16 A-fragments, PING-PONG buffered: [buf][tile][kstep][lane]
__device__ uint4          g_fh[2][16 * 64 * 32];   // hi split
__device__ uint4          g_fl[2][16 * 64 * 32];   // lo split
__device__ __nv_bfloat16  g_wh[HH * HH];    // W_hh split hi
__device__ __nv_bfloat16  g_wl[HH * HH];    // W_hh split lo
__device__ float          g_last[BB * HH];
__device__ float          g_mlp1[BB * HH];
__device__ int            g_xin[BB * SS];
__device__ int            g_len[BB];
__device__ int            g_cnt[4];
__device__ volatile int   g_sense[4];

// ---------------------------------------------------------------------------
// Preprocessing
// ---------------------------------------------------------------------------
__global__ void __launch_bounds__(256) convert_inputs(const void* xin_raw,
                                                      const void* xlen_raw) {
    long long probe = ((const long long*)xlen_raw)[0];
    bool is64 = (probe >= 1 && probe <= SS);
    int i = blockIdx.x * blockDim.x + threadIdx.x;
    if (i < BB * SS) {
        g_xin[i] = is64 ? (int)((const long long*)xin_raw)[i]
                        : ((const int*)xin_raw)[i];
    }
    if (i < BB) {
        g_len[i] = is64 ? (int)((const long long*)xlen_raw)[i]
                        : ((const int*)xlen_raw)[i];
    }
}

__global__ void __launch_bounds__(256) split_whh(const float* __restrict__ W) {
    int i = blockIdx.x * blockDim.x + threadIdx.x;
    if (i < HH * HH) {
        float w = W[i];
        __nv_bfloat16 hi = __float2bfloat16_rn(w);
        float lo = w - __bfloat162float(hi);
        g_wh[i] = hi;
        g_wl[i] = __float2bfloat16_rn(lo);
    }
}

// ---------------------------------------------------------------------------
// Generic tiled GEMM (aux)
// ---------------------------------------------------------------------------
__global__ void __launch_bounds__(256) gemm_bias_act(
    const float* __restrict__ A, const float* __restrict__ Bm,
    const float* __restrict__ bias, const float* __restrict__ bias2,
    float* __restrict__ Cout, int M, int N, int K, int act)
{
    __shared__ float As[32][33];
    __shared__ float Bs[32][65];

    const int tid = threadIdx.x;
    const int tx = tid & 15;
    const int ty = tid >> 4;
    const int m0 = blockIdx.y * 32;
    const int n0 = blockIdx.x * 64;
    const int ka = tid & 31;
    const int ra = tid >> 5;

    float acc[2][4] = {};

    for (int k0 = 0; k0 < K; k0 += 32) {
        #pragma unroll
        for (int r = 0; r < 4; r++)
            As[ka][ra + r * 8] = A[(size_t)(m0 + ra + r * 8) * K + k0 + ka];
        #pragma unroll
        for (int r = 0; r < 8; r++) {
            int n = ra + r * 8;
            float v = 0.0f;
            if (n0 + n < N) v = Bm[(size_t)(n0 + n) * K + k0 + ka];
            Bs[ka][n] = v;
        }
        __syncthreads();
        #pragma unroll
        for (int kk = 0; kk < 32; kk++) {
            float a[2], b[4];
            #pragma unroll
            for (int i = 0; i < 2; i++) a[i] = As[kk][ty * 2 + i];
            #pragma unroll
            for (int j = 0; j < 4; j++) b[j] = Bs[kk][tx * 4 + j];
            #pragma unroll
            for (int i = 0; i < 2; i++)
                #pragma unroll
                for (int j = 0; j < 4; j++)
                    acc[i][j] = fmaf(a[i], b[j], acc[i][j]);
        }
        __syncthreads();
    }

    #pragma unroll
    for (int i = 0; i < 2; i++) {
        int m = m0 + ty * 2 + i;
        if (m >= M) continue;
        #pragma unroll
        for (int j = 0; j < 4; j++) {
            int n = n0 + tx * 4 + j;
            if (n >= N) continue;
            float z = acc[i][j] + bias[n];
            if (bias2) z += bias2[n];
            if (act == 1) z = fmaxf(z, 0.0f);
            Cout[(size_t)m * N + n] = z;
        }
    }
}

// ---------------------------------------------------------------------------
// Persistent tensor-core RNN, fragment-resident h (no A staging, no k-loop
// syncs), ping-pong fragment buffers (fixes cross-CTA WAR race).
// 128 CTAs = 4 m-groups (64 rows) x 32 n-blocks (32 cols), 256 threads.
// Warps 4m x 2n, warp tile m16 x n16. W_hh (hi+lo) resident in smem k-major.
// ---------------------------------------------------------------------------
#define WS 516                       // u32 stride per W row (512 + 4 pad)
#define WH_OFF 0
#define WL_OFF (32 * WS)             // 16512
#define SMEM_U32 (2 * 32 * WS)
#define SMEM_BYTES (SMEM_U32 * 4)    // 132096

#define MMA(c, A0, A1, A2, A3, B0, B1) \
    asm volatile( \
        "mma.sync.aligned.m16n8k16.row.col.f32.bf16.bf16.f32 " \
        "{%0,%1,%2,%3}, {%4,%5,%6,%7}, {%8,%9}, {%0,%1,%2,%3};" \
        : "+f"((c)[0]), "+f"((c)[1]), "+f"((c)[2]), "+f"((c)[3]) \
        : "r"(A0), "r"(A1), "r"(A2), "r"(A3), "r"(B0), "r"(B1))

__device__ __forceinline__ uint32_t pack_bf16x2(float a, float b) {
    __nv_bfloat162 p = __floats2bfloat162_rn(a, b);
    return *(uint32_t*)&p;
}

__global__ void __launch_bounds__(256, 1) rnn_mma()
{
    extern __shared__ uint32_t sm[];

    const int tid = threadIdx.x;
    const int wid = tid >> 5;
    const int lid = tid & 31;
    const int gi = blockIdx.x >> 5;        // m-group 0..3
    const int gj = blockIdx.x & 31;        // n-block 0..31
    const int m0 = gi * 64;
    const int n0 = gj * 32;

    const int g = lid >> 2;                // 0..7
    const int q = lid & 3;                 // 0..3
    const int wm = wid & 3;                // m-warp 0..3
    const int wn = wid >> 2;               // n-warp 0..1

    // ---- load resident W (hi+lo) k-major into smem ----
    {
        const uint4* gwh = (const uint4*)g_wh;
        const uint4* gwl = (const uint4*)g_wl;
        for (int idx = tid; idx < 32 * 128; idx += 256) {
            int row = idx >> 7;            // 0..31 local n
            int slot = idx & 127;          // uint4 slot (4 kpairs)
            uint4 vh = gwh[(size_t)(n0 + row) * 128 + slot];
            uint4 vl = gwl[(size_t)(n0 + row) * 128 + slot];
            *(uint4*)(sm + WH_OFF + row * WS + slot * 4) = vh;
            *(uint4*)(sm + WL_OFF + row * WS + slot * 4) = vl;
        }
    }
    __syncthreads();

    // B fragment bases: warp covers local cols [16wn, 16wn+16) = 2 n8 tiles
    const int wb0h = (16 * wn + g) * WS + q;
    const int wb1h = wb0h + 8 * WS;
    const int wb0l = wb0h + WL_OFF;
    const int wb1l = wb1h + WL_OFF;

    // A fragment tile / lane offsets
    const int tile = 4 * gi + wm;
    const size_t rd_off = (size_t)tile * 64 * 32 + lid;

    // epilogue / writer coords
    const int me0 = m0 + 16 * wm + g;      // row g
    const int me1 = me0 + 8;               // row g+8
    const int len0 = g_len[me0];
    const int len1 = g_len[me1];
    const int colb = n0 + 16 * wn + 2 * q; // cols colb, colb+1 (+8, +9)
    const int wkstep = 2 * gj + wn;        // kstep this thread writes
    const size_t wr_off = ((size_t)tile * 64 + wkstep) * 32 + lid;

    for (int t = 0; t < SS; t++) {
        // read buffer: written at t-1 -> buffer (t-1)&1 == (t+1)&1
        const uint4* fh = g_fh[(t + 1) & 1] + rd_off;
        const uint4* fl = g_fl[(t + 1) & 1] + rd_off;
        uint4* dsth = g_fh[t & 1] + wr_off;
        uint4* dstl = g_fl[t & 1] + wr_off;

        float acc0[4] = {0.f, 0.f, 0.f, 0.f};   // n8 tile 0
        float acc1[4] = {0.f, 0.f, 0.f, 0.f};   // n8 tile 1

        if (t > 0) {
            // depth-4 register pipeline over 64 ksteps, no syncs
            uint4 bh[4], bl[4];
            #pragma unroll
            for (int p = 0; p < 4; p++) {
                bh[p] = __ldcg(fh + p * 32);
                bl[p] = __ldcg(fl + p * 32);
            }
            #pragma unroll 8
            for (int ks = 0; ks < 64; ks++) {
                const int s = ks & 3;
                const uint4 A = bh[s];
                const uint4 L = bl[s];
                const int kw = ks * 8;
                uint32_t b00h = sm[wb0h + kw];
                uint32_t b01h = sm[wb0h + kw + 4];
                uint32_t b10h = sm[wb1h + kw];
                uint32_t b11h = sm[wb1h + kw + 4];
                uint32_t b00l = sm[wb0l + kw];
                uint32_t b01l = sm[wb0l + kw + 4];
                uint32_t b10l = sm[wb1l + kw];
                uint32_t b11l = sm[wb1l + kw + 4];
                if (ks + 4 < 64) {
                    bh[s] = __ldcg(fh + (ks + 4) * 32);
                    bl[s] = __ldcg(fl + (ks + 4) * 32);
                }
                MMA(acc0, A.x, A.y, A.z, A.w, b00h, b01h);
                MMA(acc1, A.x, A.y, A.z, A.w, b10h, b11h);
                MMA(acc0, A.x, A.y, A.z, A.w, b00l, b01l);
                MMA(acc1, A.x, A.y, A.z, A.w, b10l, b11l);
                MMA(acc0, L.x, L.y, L.z, L.w, b00h, b01h);
                MMA(acc1, L.x, L.y, L.z, L.w, b10h, b11h);
            }
        }

        // ---- epilogue: rows g, g+8; cols colb..+1, colb+8..+9 ----
        {
            int xi0 = g_xin[me0 * SS + t];
            int xi1 = g_xin[me1 * SS + t];
            float2 t00 = *(const float2*)(g_T + (size_t)xi0 * HH + colb);
            float2 t01 = *(const float2*)(g_T + (size_t)xi0 * HH + colb + 8);
            float2 t10 = *(const float2*)(g_T + (size_t)xi1 * HH + colb);
            float2 t11 = *(const float2*)(g_T + (size_t)xi1 * HH + colb + 8);

            float v00 = tanhf(acc0[0] + t00.x);   // row g,   col colb
            float v01 = tanhf(acc0[1] + t00.y);   // row g,   col colb+1
            float v02 = tanhf(acc1[0] + t01.x);   // row g,   col colb+8
            float v03 = tanhf(acc1[1] + t01.y);   // row g,   col colb+9
            float v10 = tanhf(acc0[2] + t10.x);   // row g+8, col colb
            float v11 = tanhf(acc0[3] + t10.y);
            float v12 = tanhf(acc1[2] + t11.x);
            float v13 = tanhf(acc1[3] + t11.y);

            // hi split, fragment order {a0,a1,a2,a3}
            uint32_t s0 = pack_bf16x2(v00, v01);
            uint32_t s1 = pack_bf16x2(v10, v11);
            uint32_t s2 = pack_bf16x2(v02, v03);
            uint32_t s3 = pack_bf16x2(v12, v13);
            // lo residues
            __nv_bfloat162 h0 = *(__nv_bfloat162*)&s0;
            __nv_bfloat162 h1 = *(__nv_bfloat162*)&s1;
            __nv_bfloat162 h2 = *(__nv_bfloat162*)&s2;
            __nv_bfloat162 h3 = *(__nv_bfloat162*)&s3;
            uint32_t r0 = pack_bf16x2(v00 - __bfloat162float(h0.x),
                                      v01 - __bfloat162float(h0.y));
            uint32_t r1 = pack_bf16x2(v10 - __bfloat162float(h1.x),
                                      v11 - __bfloat162float(h1.y));
            uint32_t r2 = pack_bf16x2(v02 - __bfloat162float(h2.x),
                                      v03 - __bfloat162float(h2.y));
            uint32_t r3 = pack_bf16x2(v12 - __bfloat162float(h3.x),
                                      v13 - __bfloat162float(h3.y));

            *dsth = make_uint4(s0, s1, s2, s3);
            *dstl = make_uint4(r0, r1, r2, r3);

            if (t == len0 - 1) {
                *(float2*)(g_last + (size_t)me0 * HH + colb)     = make_float2(v00, v01);
                *(float2*)(g_last + (size_t)me0 * HH + colb + 8) = make_float2(v02, v03);
            }
            if (t == len1 - 1) {
                *(float2*)(g_last + (size_t)me1 * HH + colb)     = make_float2(v10, v11);
                *(float2*)(g_last + (size_t)me1 * HH + colb + 8) = make_float2(v12, v13);
            }
        }

        // ---- per-m-group barrier (32 CTAs), replay-safe ----
        __syncthreads();
        if (tid == 0) {
            __threadfence();
            int target = (t + 1) & 127;
            int arrived = atomicAdd(&g_cnt[gi], 1);
            if (arrived == 31) {
                g_cnt[gi] = 0;
                __threadfence();
                g_sense[gi] = target;
            } else {
                while (g_sense[gi] != target) { }
                __threadfence();
            }
        }
        __syncthreads();
    }
}

extern "C" void kernel_launch(void* const* d_in, const int* in_sizes, int n_in,
                              void* d_out, int out_size) {
    const void*  x_in  = d_in[0];
    const void*  xlen  = d_in[1];
    const float* emb   = (const float*)d_in[2];
    const float* W_ih  = (const float*)d_in[3];
    const float* b_ih  = (const float*)d_in[4];
    const float* W_hh  = (const float*)d_in[5];
    const float* b_hh  = (const float*)d_in[6];
    const float* W1    = (const float*)d_in[7];
    const float* b1    = (const float*)d_in[8];
    const float* W2    = (const float*)d_in[9];
    const float* b2    = (const float*)d_in[10];
    float* out = (float*)d_out;

    float *Tp, *lastp, *mlp1p;
    cudaGetSymbolAddress((void**)&Tp,    g_T);
    cudaGetSymbolAddress((void**)&lastp, g_last);
    cudaGetSymbolAddress((void**)&mlp1p, g_mlp1);

    cudaFuncSetAttribute(rnn_mma,
                         cudaFuncAttributeMaxDynamicSharedMemorySize, SMEM_BYTES);

    convert_inputs<<<(BB * SS + 255) / 256, 256>>>(x_in, xlen);
    split_whh<<<(HH * HH + 255) / 256, 256>>>(W_hh);

    // T[v][h] = emb[v]·W_ih[h] + b_ih[h] + b_hh[h]
    gemm_bias_act<<<dim3(HH / 64, VV / 32), 256>>>(emb, W_ih, b_ih, b_hh, Tp,
                                                   VV, HH, EE, 0);

    // Persistent tensor-core RNN over all 128 steps.
    rnn_mma<<<128, 256, SMEM_BYTES>>>();

    // MLP head.
    gemm_bias_act<<<dim3(HH / 64, BB / 32), 256>>>(lastp, W1, b1, nullptr, mlp1p,
                                                   BB, HH, HH, 1);
    gemm_bias_act<<<dim3(1, BB / 32), 256>>>(mlp1p, W2, b2, nullptr, out,
                                             BB, CC, HH, 0);
}

// round 17
// speedup vs baseline: 2.0326x; 1.0179x over previous
#include <cuda_runtime.h>
#include <cuda_bf16.h>
#include <math.h>
#include <stdint.h>

#define BB 256
#define SS 128
#define EE 512
#define HH 1024
#define VV 128
#define CC 18

// ---------------- device scratch (no cudaMalloc allowed) ----------------
__device__ float          g_T[VV * HH];     // T[v][h] = W_ih.emb[v] + b_ih + b_hh
// h as m16n8k16 A-fragments, PING-PONG buffered: [buf][tile][kstep][lane]
__device__ uint4          g_fh[2][16 * 64 * 32];   // hi split
__device__ uint4          g_fl[2][16 * 64 * 32];   // lo split
// W_hh as m16n8k16 B-fragments: [spl][n-block][wn*2048 + ks*32 + lane]
__device__ uint4          g_wf[2][32][4096];
__device__ float          g_last[BB * HH];
__device__ float          g_mlp1[BB * HH];
__device__ int            g_xin[BB * SS];
__device__ int            g_len[BB];
__device__ int            g_cnt[4];
__device__ volatile int   g_sense[4];

// ---------------------------------------------------------------------------
// Preprocessing
// ---------------------------------------------------------------------------
__global__ void __launch_bounds__(256) convert_inputs(const void* xin_raw,
                                                      const void* xlen_raw) {
    long long probe = ((const long long*)xlen_raw)[0];
    bool is64 = (probe >= 1 && probe <= SS);
    int i = blockIdx.x * blockDim.x + threadIdx.x;
    if (i < BB * SS) {
        g_xin[i] = is64 ? (int)((const long long*)xin_raw)[i]
                        : ((const int*)xin_raw)[i];
    }
    if (i < BB) {
        g_len[i] = is64 ? (int)((const long long*)xlen_raw)[i]
                        : ((const int*)xlen_raw)[i];
    }
}

__device__ __forceinline__ uint32_t pack_bf16x2(float a, float b) {
    __nv_bfloat162 p = __floats2bfloat162_rn(a, b);
    return *(uint32_t*)&p;
}

// Build W_hh B-fragments (hi + lo splits) in fragment-packed layout.
// uint4 = {b0_tile0, b1_tile0, b0_tile1, b1_tile1} for lane (g,q), kstep ks.
__global__ void __launch_bounds__(256) build_wfrag(const float* __restrict__ W) {
    int gid = blockIdx.x * blockDim.x + threadIdx.x;   // 0 .. 262143
    int spl  = gid >> 17;            // 0..1
    int rem  = gid & 131071;
    int gj   = rem >> 12;            // n-block 0..31
    int r    = rem & 4095;
    int wn   = r >> 11;              // 0..1
    int ks   = (r >> 5) & 63;        // kstep 0..63
    int lane = r & 31;
    int g = lane >> 2, q = lane & 3;

    int r0 = gj * 32 + wn * 16 + g;  // tile0 n-row
    int r1 = r0 + 8;                 // tile1 n-row
    int k0 = ks * 16 + 2 * q;        // b0 k-base
    int k1 = k0 + 8;                 // b1 k-base

    float w[8];
    w[0] = W[(size_t)r0 * HH + k0];     w[1] = W[(size_t)r0 * HH + k0 + 1];
    w[2] = W[(size_t)r0 * HH + k1];     w[3] = W[(size_t)r0 * HH + k1 + 1];
    w[4] = W[(size_t)r1 * HH + k0];     w[5] = W[(size_t)r1 * HH + k0 + 1];
    w[6] = W[(size_t)r1 * HH + k1];     w[7] = W[(size_t)r1 * HH + k1 + 1];

    float v[8];
    #pragma unroll
    for (int i = 0; i < 8; i++) {
        __nv_bfloat16 hi = __float2bfloat16_rn(w[i]);
        v[i] = (spl == 0) ? w[i] : (w[i] - __bfloat162float(hi));
    }
    g_wf[spl][gj][r] = make_uint4(pack_bf16x2(v[0], v[1]),
                                  pack_bf16x2(v[2], v[3]),
                                  pack_bf16x2(v[4], v[5]),
                                  pack_bf16x2(v[6], v[7]));
}

// ---------------------------------------------------------------------------
// Generic tiled GEMM (aux)
// ---------------------------------------------------------------------------
__global__ void __launch_bounds__(256) gemm_bias_act(
    const float* __restrict__ A, const float* __restrict__ Bm,
    const float* __restrict__ bias, const float* __restrict__ bias2,
    float* __restrict__ Cout, int M, int N, int K, int act)
{
    __shared__ float As[32][33];
    __shared__ float Bs[32][65];

    const int tid = threadIdx.x;
    const int tx = tid & 15;
    const int ty = tid >> 4;
    const int m0 = blockIdx.y * 32;
    const int n0 = blockIdx.x * 64;
    const int ka = tid & 31;
    const int ra = tid >> 5;

    float acc[2][4] = {};

    for (int k0 = 0; k0 < K; k0 += 32) {
        #pragma unroll
        for (int r = 0; r < 4; r++)
            As[ka][ra + r * 8] = A[(size_t)(m0 + ra + r * 8) * K + k0 + ka];
        #pragma unroll
        for (int r = 0; r < 8; r++) {
            int n = ra + r * 8;
            float v = 0.0f;
            if (n0 + n < N) v = Bm[(size_t)(n0 + n) * K + k0 + ka];
            Bs[ka][n] = v;
        }
        __syncthreads();
        #pragma unroll
        for (int kk = 0; kk < 32; kk++) {
            float a[2], b[4];
            #pragma unroll
            for (int i = 0; i < 2; i++) a[i] = As[kk][ty * 2 + i];
            #pragma unroll
            for (int j = 0; j < 4; j++) b[j] = Bs[kk][tx * 4 + j];
            #pragma unroll
            for (int i = 0; i < 2; i++)
                #pragma unroll
                for (int j = 0; j < 4; j++)
                    acc[i][j] = fmaf(a[i], b[j], acc[i][j]);
        }
        __syncthreads();
    }

    #pragma unroll
    for (int i = 0; i < 2; i++) {
        int m = m0 + ty * 2 + i;
        if (m >= M) continue;
        #pragma unroll
        for (int j = 0; j < 4; j++) {
            int n = n0 + tx * 4 + j;
            if (n >= N) continue;
            float z = acc[i][j] + bias[n];
            if (bias2) z += bias2[n];
            if (act == 1) z = fmaxf(z, 0.0f);
            Cout[(size_t)m * N + n] = z;
        }
    }
}

// ---------------------------------------------------------------------------
// Persistent tensor-core RNN: fragment-resident h (ping-pong, LDG) +
// fragment-packed W in smem (2x LDS.128 per kstep). No k-loop syncs.
// 128 CTAs = 4 m-groups (64 rows) x 32 n-blocks (32 cols), 256 threads.
// Warps 4m x 2n, warp tile m16 x n16.
// ---------------------------------------------------------------------------
#define SMEM_BYTES (8192 * 16)       // 128 KB: [spl][wn][ks][lane] uint4

#define MMA(c, A0, A1, A2, A3, B0, B1) \
    asm volatile( \
        "mma.sync.aligned.m16n8k16.row.col.f32.bf16.bf16.f32 " \
        "{%0,%1,%2,%3}, {%4,%5,%6,%7}, {%8,%9}, {%0,%1,%2,%3};" \
        : "+f"((c)[0]), "+f"((c)[1]), "+f"((c)[2]), "+f"((c)[3]) \
        : "r"(A0), "r"(A1), "r"(A2), "r"(A3), "r"(B0), "r"(B1))

__global__ void __launch_bounds__(256, 1) rnn_mma()
{
    extern __shared__ uint4 smu4[];

    const int tid = threadIdx.x;
    const int wid = tid >> 5;
    const int lid = tid & 31;
    const int gi = blockIdx.x >> 5;        // m-group 0..3
    const int gj = blockIdx.x & 31;        // n-block 0..31
    const int m0 = gi * 64;
    const int n0 = gj * 32;

    const int g = lid >> 2;                // 0..7
    const int q = lid & 3;                 // 0..3
    const int wm = wid & 3;                // m-warp 0..3
    const int wn = wid >> 2;               // n-warp 0..1

    // ---- load CTA's W fragment slice into smem (coalesced, once) ----
    for (int i = tid; i < 8192; i += 256) {
        int spl = i >> 12;
        int r   = i & 4095;
        smu4[i] = g_wf[spl][gj][r];
    }
    __syncthreads();

    // B fragment bases (uint4 index): [spl][wn][ks][lane]
    const int bh = wn * 2048 + lid;          // hi split
    const int bl = 4096 + wn * 2048 + lid;   // lo split

    // A fragment tile / lane offsets
    const int tile = 4 * gi + wm;
    const size_t rd_off = (size_t)tile * 64 * 32 + lid;

    // epilogue / writer coords
    const int me0 = m0 + 16 * wm + g;      // row g
    const int me1 = me0 + 8;               // row g+8
    const int len0 = g_len[me0];
    const int len1 = g_len[me1];
    const int colb = n0 + 16 * wn + 2 * q; // cols colb, colb+1 (+8, +9)
    const int wkstep = 2 * gj + wn;        // kstep this thread writes
    const size_t wr_off = ((size_t)tile * 64 + wkstep) * 32 + lid;

    for (int t = 0; t < SS; t++) {
        // read buffer: written at t-1 -> buffer (t-1)&1 == (t+1)&1
        const uint4* fh = g_fh[(t + 1) & 1] + rd_off;
        const uint4* fl = g_fl[(t + 1) & 1] + rd_off;
        uint4* dsth = g_fh[t & 1] + wr_off;
        uint4* dstl = g_fl[t & 1] + wr_off;

        float acc0[4] = {0.f, 0.f, 0.f, 0.f};   // n8 tile 0
        float acc1[4] = {0.f, 0.f, 0.f, 0.f};   // n8 tile 1

        if (t > 0) {
            // depth-4 register pipeline over 64 ksteps, no syncs
            uint4 ph[4], pl[4];
            #pragma unroll
            for (int p = 0; p < 4; p++) {
                ph[p] = __ldcg(fh + p * 32);
                pl[p] = __ldcg(fl + p * 32);
            }
            #pragma unroll 8
            for (int ks = 0; ks < 64; ks++) {
                const int s = ks & 3;
                const uint4 A = ph[s];
                const uint4 L = pl[s];
                const uint4 Bh = smu4[bh + ks * 32];
                const uint4 Bl = smu4[bl + ks * 32];
                if (ks + 4 < 64) {
                    ph[s] = __ldcg(fh + (ks + 4) * 32);
                    pl[s] = __ldcg(fl + (ks + 4) * 32);
                }
                MMA(acc0, A.x, A.y, A.z, A.w, Bh.x, Bh.y);
                MMA(acc1, A.x, A.y, A.z, A.w, Bh.z, Bh.w);
                MMA(acc0, A.x, A.y, A.z, A.w, Bl.x, Bl.y);
                MMA(acc1, A.x, A.y, A.z, A.w, Bl.z, Bl.w);
                MMA(acc0, L.x, L.y, L.z, L.w, Bh.x, Bh.y);
                MMA(acc1, L.x, L.y, L.z, L.w, Bh.z, Bh.w);
            }
        }

        // ---- epilogue: rows g, g+8; cols colb..+1, colb+8..+9 ----
        {
            int xi0 = g_xin[me0 * SS + t];
            int xi1 = g_xin[me1 * SS + t];
            float2 t00 = *(const float2*)(g_T + (size_t)xi0 * HH + colb);
            float2 t01 = *(const float2*)(g_T + (size_t)xi0 * HH + colb + 8);
            float2 t10 = *(const float2*)(g_T + (size_t)xi1 * HH + colb);
            float2 t11 = *(const float2*)(g_T + (size_t)xi1 * HH + colb + 8);

            float v00 = tanhf(acc0[0] + t00.x);   // row g,   col colb
            float v01 = tanhf(acc0[1] + t00.y);
            float v02 = tanhf(acc1[0] + t01.x);   // row g,   col colb+8
            float v03 = tanhf(acc1[1] + t01.y);
            float v10 = tanhf(acc0[2] + t10.x);   // row g+8, col colb
            float v11 = tanhf(acc0[3] + t10.y);
            float v12 = tanhf(acc1[2] + t11.x);
            float v13 = tanhf(acc1[3] + t11.y);

            // hi split, fragment order {a0,a1,a2,a3}
            uint32_t s0 = pack_bf16x2(v00, v01);
            uint32_t s1 = pack_bf16x2(v10, v11);
            uint32_t s2 = pack_bf16x2(v02, v03);
            uint32_t s3 = pack_bf16x2(v12, v13);
            // lo residues
            __nv_bfloat162 h0 = *(__nv_bfloat162*)&s0;
            __nv_bfloat162 h1 = *(__nv_bfloat162*)&s1;
            __nv_bfloat162 h2 = *(__nv_bfloat162*)&s2;
            __nv_bfloat162 h3 = *(__nv_bfloat162*)&s3;
            uint32_t r0 = pack_bf16x2(v00 - __bfloat162float(h0.x),
                                      v01 - __bfloat162float(h0.y));
            uint32_t r1 = pack_bf16x2(v10 - __bfloat162float(h1.x),
                                      v11 - __bfloat162float(h1.y));
            uint32_t r2 = pack_bf16x2(v02 - __bfloat162float(h2.x),
                                      v03 - __bfloat162float(h2.y));
            uint32_t r3 = pack_bf16x2(v12 - __bfloat162float(h3.x),
                                      v13 - __bfloat162float(h3.y));

            *dsth = make_uint4(s0, s1, s2, s3);
            *dstl = make_uint4(r0, r1, r2, r3);

            if (t == len0 - 1) {
                *(float2*)(g_last + (size_t)me0 * HH + colb)     = make_float2(v00, v01);
                *(float2*)(g_last + (size_t)me0 * HH + colb + 8) = make_float2(v02, v03);
            }
            if (t == len1 - 1) {
                *(float2*)(g_last + (size_t)me1 * HH + colb)     = make_float2(v10, v11);
                *(float2*)(g_last + (size_t)me1 * HH + colb + 8) = make_float2(v12, v13);
            }
        }

        // ---- per-m-group barrier (32 CTAs), replay-safe ----
        __syncthreads();
        if (tid == 0) {
            __threadfence();
            int target = (t + 1) & 127;
            int arrived = atomicAdd(&g_cnt[gi], 1);
            if (arrived == 31) {
                g_cnt[gi] = 0;
                __threadfence();
                g_sense[gi] = target;
            } else {
                while (g_sense[gi] != target) { }
                __threadfence();
            }
        }
        __syncthreads();
    }
}

extern "C" void kernel_launch(void* const* d_in, const int* in_sizes, int n_in,
                              void* d_out, int out_size) {
    const void*  x_in  = d_in[0];
    const void*  xlen  = d_in[1];
    const float* emb   = (const float*)d_in[2];
    const float* W_ih  = (const float*)d_in[3];
    const float* b_ih  = (const float*)d_in[4];
    const float* W_hh  = (const float*)d_in[5];
    const float* b_hh  = (const float*)d_in[6];
    const float* W1    = (const float*)d_in[7];
    const float* b1    = (const float*)d_in[8];
    const float* W2    = (const float*)d_in[9];
    const float* b2    = (const float*)d_in[10];
    float* out = (float*)d_out;

    float *Tp, *lastp, *mlp1p;
    cudaGetSymbolAddress((void**)&Tp,    g_T);
    cudaGetSymbolAddress((void**)&lastp, g_last);
    cudaGetSymbolAddress((void**)&mlp1p, g_mlp1);

    cudaFuncSetAttribute(rnn_mma,
                         cudaFuncAttributeMaxDynamicSharedMemorySize, SMEM_BYTES);

    convert_inputs<<<(BB * SS + 255) / 256, 256>>>(x_in, xlen);
    build_wfrag<<<1024, 256>>>(W_hh);

    // T[v][h] = emb[v]·W_ih[h] + b_ih[h] + b_hh[h]
    gemm_bias_act<<<dim3(HH / 64, VV / 32), 256>>>(emb, W_ih, b_ih, b_hh, Tp,
                                                   VV, HH, EE, 0);

    // Persistent tensor-core RNN over all 128 steps.
    rnn_mma<<<128, 256, SMEM_BYTES>>>();

    // MLP head.
    gemm_bias_act<<<dim3(HH / 64, BB / 32), 256>>>(lastp, W1, b1, nullptr, mlp1p,
                                                   BB, HH, HH, 1);
    gemm_bias_act<<<dim3(1, BB / 32), 256>>>(mlp1p, W2, b2, nullptr, out,
                                             BB, CC, HH, 0);
}